// round 15
// baseline (speedup 1.0000x reference)
#include <cuda_runtime.h>
#include <math.h>

#define Bb   8
#define Cc   64
#define Nn   2048
#define KNB  32
#define NHEADS 8
#define EPSBN 1e-5f
#define NSLOPE 0.2f

// ---------------- scratch (device globals; no runtime allocation) ----------------
__device__ float g_xx[Bb * Nn];
__device__ float g_D[(size_t)Bb * Nn * Nn];             // 128 MB distance matrix
__device__ int   g_idx[Bb * Nn * KNB];
__device__ float g_Qt[(size_t)Bb * Nn * Cc];            // (B,N,64) point-major
__device__ float g_Kt[(size_t)Bb * Nn * Cc];
__device__ float g_Vt[(size_t)Bb * Nn * Cc];
__device__ float g_y [(size_t)Bb * Cc * Nn];
__device__ float g_y2[(size_t)Bb * Cc * Nn];
__device__ float g_mu1[Cc], g_rs1[Cc], g_mu2[Cc], g_rs2[Cc];
__device__ double g_ps [2][Cc][Bb];
__device__ double g_ps2[2][Cc][Bb];
__device__ int    g_cnt[2];                              // zero-init; self-resetting

// ---------------- packed f32x2 helpers (sm_103a FFMA2/FADD2 path) ----------------
__device__ __forceinline__ unsigned long long pack2(float x, float y) {
    unsigned long long r;
    asm("mov.b64 %0, {%1, %2};" : "=l"(r) : "f"(x), "f"(y));
    return r;
}
__device__ __forceinline__ unsigned long long ffma2(unsigned long long a,
                                                    unsigned long long b,
                                                    unsigned long long c) {
    unsigned long long d;
    asm("fma.rn.f32x2 %0, %1, %2, %3;" : "=l"(d) : "l"(a), "l"(b), "l"(c));
    return d;
}
__device__ __forceinline__ void unpack2(unsigned long long v, float& lo, float& hi) {
    asm("mov.b64 {%0, %1}, %2;" : "=f"(lo), "=f"(hi) : "l"(v));
}

// ---------------- 1. fused squared norms + Q/K/V projections ----------------
extern __shared__ float dynsmem[];
__global__ void qkv_kernel(const float* __restrict__ x,
                           const float* __restrict__ Wq,
                           const float* __restrict__ Wk,
                           const float* __restrict__ Wv) {
    float (*xs)[68] = (float(*)[68])dynsmem;
    float (*Wt)[68] = (float(*)[68])(dynsmem + 64 * 68);
    int b = blockIdx.y, n0 = blockIdx.x * 64;
    int t = threadIdx.x;
    const float* xb = x + (size_t)b * Cc * Nn;
    for (int idx = t; idx < 4096; idx += 256) {
        int c = idx >> 6, p = idx & 63;
        xs[c][p] = xb[c * Nn + n0 + p];
    }
    const float* Ws[3] = {Wq, Wk, Wv};
#pragma unroll
    for (int m = 0; m < 3; m++)
        for (int idx = t; idx < 4096; idx += 256) {
            int o = idx >> 6, c = idx & 63;
            Wt[m * 64 + c][o] = Ws[m][idx];
        }
    __syncthreads();

    if (t < 64) {                                  // squared norms for these 64 points
        float s = 0.f;
#pragma unroll
        for (int c = 0; c < 64; c++) s = fmaf(xs[c][t], xs[c][t], s);
        g_xx[b * Nn + n0 + t] = s;
    }

    int tx = t & 15, ty = t >> 4;
    float acc[3][4][4] = {};
    for (int c = 0; c < 64; c++) {
        float4 xv4 = *(const float4*)&xs[c][tx * 4];
        float xr[4] = {xv4.x, xv4.y, xv4.z, xv4.w};
#pragma unroll
        for (int m = 0; m < 3; m++) {
            float4 wv4 = *(const float4*)&Wt[m * 64 + c][ty * 4];
            float wr[4] = {wv4.x, wv4.y, wv4.z, wv4.w};
#pragma unroll
            for (int oi = 0; oi < 4; oi++)
#pragma unroll
                for (int pj = 0; pj < 4; pj++)
                    acc[m][oi][pj] = fmaf(wr[oi], xr[pj], acc[m][oi][pj]);
        }
    }
    float* Olist[3] = {g_Qt, g_Kt, g_Vt};
#pragma unroll
    for (int m = 0; m < 3; m++)
#pragma unroll
        for (int pj = 0; pj < 4; pj++) {
            int p = n0 + tx * 4 + pj;
            float4 val = make_float4(acc[m][0][pj], acc[m][1][pj], acc[m][2][pj], acc[m][3][pj]);
            *(float4*)&Olist[m][((size_t)(b * Nn + p)) * 64 + ty * 4] = val;
        }
}

// ---------------- 2. neg squared distance matrix ----------------
__global__ void __launch_bounds__(256, 2) dist_kernel(const float* __restrict__ x) {
    int b = blockIdx.z;
    int p = blockIdx.x, bi = 0;
    while (p >= 16 - bi) { p -= 16 - bi; bi++; }
    int bj = bi + p;
    int i0 = bi * 128, j0 = bj * 128;

    __shared__ float As[32][132];
    __shared__ float Bs[32][132];
    int t = threadIdx.x;
    int tx = t & 15, ty = t >> 4;
    const float* xb = x + (size_t)b * Cc * Nn;

    unsigned long long acc2[4][8];
#pragma unroll
    for (int ip = 0; ip < 4; ip++)
#pragma unroll
        for (int j = 0; j < 8; j++) acc2[ip][j] = 0ull;

    for (int kc = 0; kc < Cc; kc += 32) {
        __syncthreads();
        for (int idx = t; idx < 32 * 128; idx += 256) {
            int c = idx >> 7, q = idx & 127;
            As[c][q] = xb[(kc + c) * Nn + i0 + q];
            Bs[c][q] = xb[(kc + c) * Nn + j0 + q];
        }
        __syncthreads();
#pragma unroll
        for (int c = 0; c < 32; c++) {
            ulonglong2 ap0 = *(const ulonglong2*)&As[c][ty * 8];
            ulonglong2 ap1 = *(const ulonglong2*)&As[c][ty * 8 + 4];
            unsigned long long ap[4] = {ap0.x, ap0.y, ap1.x, ap1.y};
            float4 b0 = *(const float4*)&Bs[c][tx * 8];
            float4 b1 = *(const float4*)&Bs[c][tx * 8 + 4];
            float bv[8] = {b0.x, b0.y, b0.z, b0.w, b1.x, b1.y, b1.z, b1.w};
            unsigned long long bc[8];
#pragma unroll
            for (int j = 0; j < 8; j++) bc[j] = pack2(bv[j], bv[j]);
#pragma unroll
            for (int ip = 0; ip < 4; ip++)
#pragma unroll
                for (int j = 0; j < 8; j++)
                    acc2[ip][j] = ffma2(ap[ip], bc[j], acc2[ip][j]);
        }
    }

    float acc[8][8];
#pragma unroll
    for (int ip = 0; ip < 4; ip++)
#pragma unroll
        for (int j = 0; j < 8; j++)
            unpack2(acc2[ip][j], acc[2 * ip][j], acc[2 * ip + 1][j]);

    float xi[8], xj[8];
#pragma unroll
    for (int ii = 0; ii < 8; ii++) xi[ii] = g_xx[b * Nn + i0 + ty * 8 + ii];
#pragma unroll
    for (int jj = 0; jj < 8; jj++) xj[jj] = g_xx[b * Nn + j0 + tx * 8 + jj];

    float v[8][8];
#pragma unroll
    for (int ii = 0; ii < 8; ii++)
#pragma unroll
        for (int jj = 0; jj < 8; jj++)
            v[ii][jj] = 2.f * acc[ii][jj] - xi[ii] - xj[jj];

#pragma unroll
    for (int ii = 0; ii < 8; ii++) {
        size_t base = ((size_t)b * Nn + i0 + ty * 8 + ii) * Nn + j0 + tx * 8;
        *(float4*)&g_D[base]     = make_float4(v[ii][0], v[ii][1], v[ii][2], v[ii][3]);
        *(float4*)&g_D[base + 4] = make_float4(v[ii][4], v[ii][5], v[ii][6], v[ii][7]);
    }
    if (bi != bj) {
#pragma unroll
        for (int jj = 0; jj < 8; jj++) {
            size_t base = ((size_t)b * Nn + j0 + tx * 8 + jj) * Nn + i0 + ty * 8;
            *(float4*)&g_D[base]     = make_float4(v[0][jj], v[1][jj], v[2][jj], v[3][jj]);
            *(float4*)&g_D[base + 4] = make_float4(v[4][jj], v[5][jj], v[6][jj], v[7][jj]);
        }
    }
}

// ---------------- 3. top-32 per row: 2-level radix + warp micro-select ----------------
__global__ void topk_kernel() {
    int row = blockIdx.x;
    int t = threadIdx.x;                    // 256 threads
    int lane = t & 31, w = t >> 5;
    const float* Drow = g_D + (size_t)row * Nn;

    unsigned int u[8];
    {
        float4 f0 = *(const float4*)(Drow + 8 * t);
        float4 f1 = *(const float4*)(Drow + 8 * t + 4);
        float fv[8] = {f0.x, f0.y, f0.z, f0.w, f1.x, f1.y, f1.z, f1.w};
#pragma unroll
        for (int r = 0; r < 8; r++) {
            unsigned int bits = __float_as_uint(fv[r]);
            u[r] = (bits & 0x80000000u) ? ~bits : (bits | 0x80000000u);
        }
    }

    __shared__ unsigned int hist[256];
    __shared__ unsigned int warpsum[8];
    __shared__ unsigned int sb, sabove;
    __shared__ unsigned long long cand[2048];
    __shared__ int selCnt, candCnt, needSh;

    unsigned int prefix = 0, pmask = 0;
    int need = KNB;

#pragma unroll
    for (int lvl = 0; lvl < 2; lvl++) {
        int shift = 24 - 8 * lvl;
        hist[t] = 0;
        __syncthreads();
#pragma unroll
        for (int r = 0; r < 8; r++)
            if ((u[r] & pmask) == prefix)
                atomicAdd(&hist[(u[r] >> shift) & 255u], 1u);
        __syncthreads();
        unsigned int hv = hist[t];
        unsigned int v = hv;
#pragma unroll
        for (int s = 1; s < 32; s <<= 1) {
            unsigned int o = __shfl_down_sync(0xffffffffu, v, s);
            if (lane + s < 32) v += o;
        }
        if (lane == 0) warpsum[w] = v;
        __syncthreads();
        unsigned int addw = 0;
        for (int j = w + 1; j < 8; j++) addw += warpsum[j];
        unsigned int hs_t = v + addw;
        unsigned int above = hs_t - hv;
        if (hs_t >= (unsigned int)need && above < (unsigned int)need) {
            sb = (unsigned int)t; sabove = above;
        }
        __syncthreads();
        prefix |= sb << shift;
        pmask  |= 0xFFu << shift;
        need   -= (int)sabove;
        __syncthreads();
    }

    if (t == 0) { selCnt = 0; candCnt = 0; needSh = need; }
    __syncthreads();
#pragma unroll
    for (int r = 0; r < 8; r++) {
        int gi = 8 * t + r;
        unsigned int masked = u[r] & pmask;
        if (masked > prefix) {
            int pos = atomicAdd(&selCnt, 1);
            g_idx[row * KNB + pos] = gi;
        } else if (masked == prefix) {
            int pos = atomicAdd(&candCnt, 1);
            cand[pos] = ((unsigned long long)u[r] << 32) | (unsigned int)(2047 - gi);
        }
    }
    __syncthreads();

    if (w == 0) {
        int m = candCnt;
        int base = selCnt;
        int nd = needSh;
        for (int p2 = 0; p2 < nd; p2++) {
            unsigned long long best = 0ull;
            for (int j = lane; j < m; j += 32)
                best = (cand[j] > best) ? cand[j] : best;
#pragma unroll
            for (int s = 16; s; s >>= 1) {
                unsigned long long o = __shfl_xor_sync(0xffffffffu, best, s);
                best = (o > best) ? o : best;
            }
            if (lane == 0)
                g_idx[row * KNB + base + p2] = 2047 - (int)(best & 0xFFFFFFFFull);
            for (int j = lane; j < m; j += 32)
                if (cand[j] == best) cand[j] = 0ull;
        }
    }
}

// ---------------- 5. attention: gather-fused energies, register-resident V ----------------
// softmax(q·(k-kc)) == softmax(q·k); sum_k a_k (v_k - vc) == (sum_k a_k v_k) - vc
__global__ void attn_kernel(const float* __restrict__ x) {
    int row = blockIdx.x;
    int b = row >> 11, n = row & (Nn - 1);
    int t = threadIdx.x;                       // 256 = 8 warps
    int w = t >> 5, l = t & 31;
    __shared__ float qv[64];
    __shared__ int   sid[32];
    __shared__ float Es[32][9];                // energies [neighbor][head], padded
    __shared__ float Aw[32][9];                // softmax weights
    __shared__ float Op[8][64];                // per-warp partial outputs
    if (t < 32)                   sid[t]     = g_idx[row * KNB + t];
    else if (t >= 64 && t < 128)  qv[t - 64] = g_Qt[(size_t)row * 64 + (t - 64)];
    __syncthreads();

    int c4 = l & 15;                           // 4-channel chunk index 0..15
    int ch = c4 * 4;
    int head = c4 >> 1;
    float4 q4 = *(const float4*)&qv[ch];

    // Phase A: coalesced K/V gather; energies computed in the staging lanes.
    float4 vreg[2];
    int rr[2];
#pragma unroll
    for (int it = 0; it < 2; it++) {
        int r = 2 * w + (l >> 4) + 16 * it;    // this lane's neighbor row
        rr[it] = r;
        size_t base = ((size_t)(b * Nn + sid[r])) * 64 + ch;
        float4 k4 = *(const float4*)&g_Kt[base];
        vreg[it]  = *(const float4*)&g_Vt[base];
        float e = 0.f;
        e = fmaf(q4.x, k4.x, e);
        e = fmaf(q4.y, k4.y, e);
        e = fmaf(q4.z, k4.z, e);
        e = fmaf(q4.w, k4.w, e);
        e += __shfl_xor_sync(0xffffffffu, e, 1);   // fold chunk pair -> full 8-dim dot
        if ((c4 & 1) == 0) Es[r][head] = e;
    }
    __syncthreads();

    // Phase B: warp w = head w softmax over 32 neighbors
    {
        float e = Es[l][w] * 0.3535533905932738f;  // 1/sqrt(8)
        float m = e;
#pragma unroll
        for (int s = 16; s; s >>= 1) m = fmaxf(m, __shfl_xor_sync(0xffffffffu, m, s));
        float ex = __expf(e - m);
        float ssum = ex;
#pragma unroll
        for (int s = 16; s; s >>= 1) ssum += __shfl_xor_sync(0xffffffffu, ssum, s);
        Aw[l][w] = ex / ssum;
    }
    __syncthreads();

    // Phase C: weighted V sum from registers
    float4 acc = make_float4(0.f, 0.f, 0.f, 0.f);
#pragma unroll
    for (int it = 0; it < 2; it++) {
        float a = Aw[rr[it]][head];
        acc.x = fmaf(a, vreg[it].x, acc.x);
        acc.y = fmaf(a, vreg[it].y, acc.y);
        acc.z = fmaf(a, vreg[it].z, acc.z);
        acc.w = fmaf(a, vreg[it].w, acc.w);
    }
    acc.x += __shfl_down_sync(0xffffffffu, acc.x, 16);
    acc.y += __shfl_down_sync(0xffffffffu, acc.y, 16);
    acc.z += __shfl_down_sync(0xffffffffu, acc.z, 16);
    acc.w += __shfl_down_sync(0xffffffffu, acc.w, 16);
    if (l < 16) *(float4*)&Op[w][ch] = acc;
    __syncthreads();

    if (t < 64) {                              // fold 8 warps + centering + residual
        float s = 0.f;
#pragma unroll
        for (int j = 0; j < 8; j++) s += Op[j][t];
        s -= g_Vt[(size_t)row * 64 + t];       // center-V correction
        size_t gi = (size_t)b * Cc * Nn + (size_t)t * Nn + n;
        g_y[gi] = x[gi] + s;
    }
}

// ---------------- 6/8. BN stats, single kernel with last-block finalize ----------------
__global__ void statsA_kernel(int which) {
    const float* in = which ? g_y2 : g_y;
    int c = blockIdx.x, b = blockIdx.y, t = threadIdx.x;
    int lane = t & 31, w = t >> 5;
    const float* p = in + (size_t)b * Cc * Nn + (size_t)c * Nn;
    double s = 0.0, s2 = 0.0;
    for (int n = t; n < Nn; n += 256) { float v = p[n]; s += v; s2 += (double)v * v; }
#pragma unroll
    for (int o = 16; o; o >>= 1) {
        s  += __shfl_down_sync(0xffffffffu, s, o);
        s2 += __shfl_down_sync(0xffffffffu, s2, o);
    }
    __shared__ double ws[8], ws2[8];
    __shared__ int isLast;
    if (lane == 0) { ws[w] = s; ws2[w] = s2; }
    __syncthreads();
    if (t == 0) {
        double ts = 0.0, ts2 = 0.0;
        for (int j = 0; j < 8; j++) { ts += ws[j]; ts2 += ws2[j]; }
        g_ps[which][c][b] = ts;
        g_ps2[which][c][b] = ts2;
        __threadfence();
        int v = atomicAdd(&g_cnt[which], 1);
        isLast = (v == Cc * Bb - 1);
    }
    __syncthreads();
    if (isLast) {
        if (t < Cc) {
            double ts = 0.0, ts2 = 0.0;
            for (int j = 0; j < Bb; j++) { ts += g_ps[which][t][j]; ts2 += g_ps2[which][t][j]; }
            double m = ts / (Bb * Nn);
            double var = ts2 / (Bb * Nn) - m * m;
            (which ? g_mu2 : g_mu1)[t] = (float)m;
            (which ? g_rs2 : g_rs1)[t] = (float)(1.0 / sqrt(var + (double)EPSBN));
        }
        __syncthreads();
        if (t == 0) g_cnt[which] = 0;           // self-reset for next graph replay
    }
}

// ---------------- 7. BN1 apply + FFN + residual ----------------
__global__ void ffn_kernel(const float* __restrict__ W1, const float* __restrict__ W2,
                           const float* __restrict__ g1, const float* __restrict__ b1) {
    int blk = blockIdx.x;
    int b = blk / (Nn / 16);
    int n0 = (blk % (Nn / 16)) * 16;
    __shared__ float Wbuf[128 * 64];
    __shared__ float x1s[64][17];
    __shared__ float hs[128][17];
    int t = threadIdx.x;

    for (int idx = t; idx < 64 * 16; idx += 256) {
        int c = idx >> 4, p = idx & 15;
        float v = g_y[(size_t)b * Cc * Nn + (size_t)c * Nn + n0 + p];
        x1s[c][p] = (v - g_mu1[c]) * g_rs1[c] * g1[c] + b1[c];
    }
    for (int idx = t; idx < 128 * 64; idx += 256) Wbuf[idx] = W1[idx];
    __syncthreads();

    int p = t & 15, obase = t >> 4;
    float hreg[8];
#pragma unroll
    for (int i = 0; i < 8; i++) {
        int o = obase + 16 * i;
        float s = 0.f;
#pragma unroll
        for (int c = 0; c < 64; c++) s = fmaf(Wbuf[o * 64 + c], x1s[c][p], s);
        hreg[i] = (s >= 0.f) ? s : NSLOPE * s;
    }
#pragma unroll
    for (int i = 0; i < 8; i++) hs[obase + 16 * i][p] = hreg[i];
    __syncthreads();
    for (int idx = t; idx < 64 * 128; idx += 256) Wbuf[idx] = W2[idx];
    __syncthreads();

#pragma unroll
    for (int i = 0; i < 4; i++) {
        int c = obase + 16 * i;
        float s = 0.f;
#pragma unroll
        for (int o = 0; o < 128; o++) s = fmaf(Wbuf[c * 128 + o], hs[o][p], s);
        g_y2[(size_t)b * Cc * Nn + (size_t)c * Nn + n0 + p] = x1s[c][p] + s;
    }
}

// ---------------- 9. final BN apply (float4) ----------------
__global__ void apply_kernel(const float* __restrict__ g2, const float* __restrict__ b2,
                             float* __restrict__ out) {
    int i4 = blockIdx.x * blockDim.x + threadIdx.x;      // float4 index
    if (i4 < (Bb * Cc * Nn) / 4) {
        int c = ((i4 * 4) / Nn) & (Cc - 1);
        float4 v = *(const float4*)&g_y2[(size_t)i4 * 4];
        float sc = g_rs2[c] * g2[c], mu = g_mu2[c], bb = b2[c];
        float4 o = make_float4((v.x - mu) * sc + bb, (v.y - mu) * sc + bb,
                               (v.z - mu) * sc + bb, (v.w - mu) * sc + bb);
        *(float4*)&out[(size_t)i4 * 4] = o;
    }
}

// ---------------- launch ----------------
extern "C" void kernel_launch(void* const* d_in, const int* in_sizes, int n_in,
                              void* d_out, int out_size) {
    const float* x  = (const float*)d_in[0];
    const float* Wq = (const float*)d_in[1];
    const float* Wk = (const float*)d_in[2];
    const float* Wv = (const float*)d_in[3];
    const float* W1 = (const float*)d_in[4];
    const float* W2 = (const float*)d_in[5];
    const float* g1 = (const float*)d_in[6];
    const float* b1 = (const float*)d_in[7];
    const float* g2 = (const float*)d_in[8];
    const float* b2 = (const float*)d_in[9];
    float* out = (float*)d_out;

    const int qkv_smem = (64 * 68 + 3 * 64 * 68) * 4;    // 69632 B
    cudaFuncSetAttribute(qkv_kernel, cudaFuncAttributeMaxDynamicSharedMemorySize, qkv_smem);

    qkv_kernel<<<dim3(Nn / 64, Bb), 256, qkv_smem>>>(x, Wq, Wk, Wv);
    dist_kernel<<<dim3(136, 1, Bb), 256>>>(x);
    topk_kernel<<<Bb * Nn, 256>>>();
    attn_kernel<<<Bb * Nn, 256>>>(x);
    statsA_kernel<<<dim3(Cc, Bb), 256>>>(0);
    ffn_kernel<<<Bb * Nn / 16, 256>>>(W1, W2, g1, b1);
    statsA_kernel<<<dim3(Cc, Bb), 256>>>(1);
    apply_kernel<<<(Bb * Cc * Nn / 4 + 255) / 256, 256>>>(g2, b2, out);
}

// round 16
// speedup vs baseline: 1.4492x; 1.4492x over previous
#include <cuda_runtime.h>
#include <math.h>

#define Bb   8
#define Cc   64
#define Nn   2048
#define KNB  32
#define NHEADS 8
#define EPSBN 1e-5f
#define NSLOPE 0.2f

// ---------------- scratch (device globals; no runtime allocation) ----------------
__device__ float g_xx[Bb * Nn];
__device__ float g_D[(size_t)Bb * Nn * Nn];             // 128 MB distance matrix
__device__ int   g_idx[Bb * Nn * KNB];
__device__ float g_Qt[(size_t)Bb * Nn * Cc];            // (B,N,64) point-major
__device__ float g_Kt[(size_t)Bb * Nn * Cc];
__device__ float g_Vt[(size_t)Bb * Nn * Cc];
__device__ float g_y [(size_t)Bb * Cc * Nn];
__device__ float g_y2[(size_t)Bb * Cc * Nn];
__device__ float g_mu1[Cc], g_rs1[Cc], g_mu2[Cc], g_rs2[Cc];
__device__ double g_ps [2][Cc][Bb];
__device__ double g_ps2[2][Cc][Bb];
__device__ int    g_cnt[2];                              // zero-init; self-resetting

// ---------------- packed f32x2 helpers (sm_103a FFMA2/FADD2 path) ----------------
__device__ __forceinline__ unsigned long long pack2(float x, float y) {
    unsigned long long r;
    asm("mov.b64 %0, {%1, %2};" : "=l"(r) : "f"(x), "f"(y));
    return r;
}
__device__ __forceinline__ unsigned long long ffma2(unsigned long long a,
                                                    unsigned long long b,
                                                    unsigned long long c) {
    unsigned long long d;
    asm("fma.rn.f32x2 %0, %1, %2, %3;" : "=l"(d) : "l"(a), "l"(b), "l"(c));
    return d;
}
__device__ __forceinline__ unsigned long long addf2(unsigned long long a,
                                                    unsigned long long b) {
    unsigned long long d;
    asm("add.rn.f32x2 %0, %1, %2;" : "=l"(d) : "l"(a), "l"(b));
    return d;
}
__device__ __forceinline__ void unpack2(unsigned long long v, float& lo, float& hi) {
    asm("mov.b64 {%0, %1}, %2;" : "=f"(lo), "=f"(hi) : "l"(v));
}

// ---------------- 1. fused squared norms + Q/K/V projections ----------------
extern __shared__ float dynsmem[];
__global__ void qkv_kernel(const float* __restrict__ x,
                           const float* __restrict__ Wq,
                           const float* __restrict__ Wk,
                           const float* __restrict__ Wv) {
    float (*xs)[68] = (float(*)[68])dynsmem;
    float (*Wt)[68] = (float(*)[68])(dynsmem + 64 * 68);
    int b = blockIdx.y, n0 = blockIdx.x * 64;
    int t = threadIdx.x;
    const float* xb = x + (size_t)b * Cc * Nn;
    for (int idx = t; idx < 4096; idx += 256) {
        int c = idx >> 6, p = idx & 63;
        xs[c][p] = xb[c * Nn + n0 + p];
    }
    const float* Ws[3] = {Wq, Wk, Wv};
#pragma unroll
    for (int m = 0; m < 3; m++)
        for (int idx = t; idx < 4096; idx += 256) {
            int o = idx >> 6, c = idx & 63;
            Wt[m * 64 + c][o] = Ws[m][idx];
        }
    __syncthreads();

    if (t < 64) {                                  // squared norms for these 64 points
        float s = 0.f;
#pragma unroll
        for (int c = 0; c < 64; c++) s = fmaf(xs[c][t], xs[c][t], s);
        g_xx[b * Nn + n0 + t] = s;
    }

    int tx = t & 15, ty = t >> 4;
    float acc[3][4][4] = {};
    for (int c = 0; c < 64; c++) {
        float4 xv4 = *(const float4*)&xs[c][tx * 4];
        float xr[4] = {xv4.x, xv4.y, xv4.z, xv4.w};
#pragma unroll
        for (int m = 0; m < 3; m++) {
            float4 wv4 = *(const float4*)&Wt[m * 64 + c][ty * 4];
            float wr[4] = {wv4.x, wv4.y, wv4.z, wv4.w};
#pragma unroll
            for (int oi = 0; oi < 4; oi++)
#pragma unroll
                for (int pj = 0; pj < 4; pj++)
                    acc[m][oi][pj] = fmaf(wr[oi], xr[pj], acc[m][oi][pj]);
        }
    }
    float* Olist[3] = {g_Qt, g_Kt, g_Vt};
#pragma unroll
    for (int m = 0; m < 3; m++)
#pragma unroll
        for (int pj = 0; pj < 4; pj++) {
            int p = n0 + tx * 4 + pj;
            float4 val = make_float4(acc[m][0][pj], acc[m][1][pj], acc[m][2][pj], acc[m][3][pj]);
            *(float4*)&Olist[m][((size_t)(b * Nn + p)) * 64 + ty * 4] = val;
        }
}

// ---------------- 2. neg squared distance matrix ----------------
__global__ void __launch_bounds__(256, 2) dist_kernel(const float* __restrict__ x) {
    int b = blockIdx.z;
    int p = blockIdx.x, bi = 0;
    while (p >= 16 - bi) { p -= 16 - bi; bi++; }
    int bj = bi + p;
    int i0 = bi * 128, j0 = bj * 128;

    __shared__ float As[32][132];
    __shared__ float Bs[32][132];
    int t = threadIdx.x;
    int tx = t & 15, ty = t >> 4;
    const float* xb = x + (size_t)b * Cc * Nn;

    unsigned long long acc2[4][8];
#pragma unroll
    for (int ip = 0; ip < 4; ip++)
#pragma unroll
        for (int j = 0; j < 8; j++) acc2[ip][j] = 0ull;

    for (int kc = 0; kc < Cc; kc += 32) {
        __syncthreads();
        for (int idx = t; idx < 32 * 128; idx += 256) {
            int c = idx >> 7, q = idx & 127;
            As[c][q] = xb[(kc + c) * Nn + i0 + q];
            Bs[c][q] = xb[(kc + c) * Nn + j0 + q];
        }
        __syncthreads();
#pragma unroll
        for (int c = 0; c < 32; c++) {
            ulonglong2 ap0 = *(const ulonglong2*)&As[c][ty * 8];
            ulonglong2 ap1 = *(const ulonglong2*)&As[c][ty * 8 + 4];
            unsigned long long ap[4] = {ap0.x, ap0.y, ap1.x, ap1.y};
            float4 b0 = *(const float4*)&Bs[c][tx * 8];
            float4 b1 = *(const float4*)&Bs[c][tx * 8 + 4];
            float bv[8] = {b0.x, b0.y, b0.z, b0.w, b1.x, b1.y, b1.z, b1.w};
            unsigned long long bc[8];
#pragma unroll
            for (int j = 0; j < 8; j++) bc[j] = pack2(bv[j], bv[j]);
#pragma unroll
            for (int ip = 0; ip < 4; ip++)
#pragma unroll
                for (int j = 0; j < 8; j++)
                    acc2[ip][j] = ffma2(ap[ip], bc[j], acc2[ip][j]);
        }
    }

    float acc[8][8];
#pragma unroll
    for (int ip = 0; ip < 4; ip++)
#pragma unroll
        for (int j = 0; j < 8; j++)
            unpack2(acc2[ip][j], acc[2 * ip][j], acc[2 * ip + 1][j]);

    float xi[8], xj[8];
#pragma unroll
    for (int ii = 0; ii < 8; ii++) xi[ii] = g_xx[b * Nn + i0 + ty * 8 + ii];
#pragma unroll
    for (int jj = 0; jj < 8; jj++) xj[jj] = g_xx[b * Nn + j0 + tx * 8 + jj];

    float v[8][8];
#pragma unroll
    for (int ii = 0; ii < 8; ii++)
#pragma unroll
        for (int jj = 0; jj < 8; jj++)
            v[ii][jj] = 2.f * acc[ii][jj] - xi[ii] - xj[jj];

#pragma unroll
    for (int ii = 0; ii < 8; ii++) {
        size_t base = ((size_t)b * Nn + i0 + ty * 8 + ii) * Nn + j0 + tx * 8;
        *(float4*)&g_D[base]     = make_float4(v[ii][0], v[ii][1], v[ii][2], v[ii][3]);
        *(float4*)&g_D[base + 4] = make_float4(v[ii][4], v[ii][5], v[ii][6], v[ii][7]);
    }
    if (bi != bj) {
#pragma unroll
        for (int jj = 0; jj < 8; jj++) {
            size_t base = ((size_t)b * Nn + j0 + tx * 8 + jj) * Nn + i0 + ty * 8;
            *(float4*)&g_D[base]     = make_float4(v[0][jj], v[1][jj], v[2][jj], v[3][jj]);
            *(float4*)&g_D[base + 4] = make_float4(v[4][jj], v[5][jj], v[6][jj], v[7][jj]);
        }
    }
}

// ---------------- 3. top-32 per row: 2-level radix + warp micro-select ----------------
__global__ void topk_kernel() {
    int row = blockIdx.x;
    int t = threadIdx.x;                    // 256 threads
    int lane = t & 31, w = t >> 5;
    const float* Drow = g_D + (size_t)row * Nn;

    unsigned int u[8];
    {
        float4 f0 = *(const float4*)(Drow + 8 * t);
        float4 f1 = *(const float4*)(Drow + 8 * t + 4);
        float fv[8] = {f0.x, f0.y, f0.z, f0.w, f1.x, f1.y, f1.z, f1.w};
#pragma unroll
        for (int r = 0; r < 8; r++) {
            unsigned int bits = __float_as_uint(fv[r]);
            u[r] = (bits & 0x80000000u) ? ~bits : (bits | 0x80000000u);
        }
    }

    __shared__ unsigned int hist[256];
    __shared__ unsigned int warpsum[8];
    __shared__ unsigned int sb, sabove;
    __shared__ unsigned long long cand[2048];
    __shared__ int selCnt, candCnt, needSh;

    unsigned int prefix = 0, pmask = 0;
    int need = KNB;

#pragma unroll
    for (int lvl = 0; lvl < 2; lvl++) {
        int shift = 24 - 8 * lvl;
        hist[t] = 0;
        __syncthreads();
#pragma unroll
        for (int r = 0; r < 8; r++)
            if ((u[r] & pmask) == prefix)
                atomicAdd(&hist[(u[r] >> shift) & 255u], 1u);
        __syncthreads();
        unsigned int hv = hist[t];
        unsigned int v = hv;
#pragma unroll
        for (int s = 1; s < 32; s <<= 1) {
            unsigned int o = __shfl_down_sync(0xffffffffu, v, s);
            if (lane + s < 32) v += o;
        }
        if (lane == 0) warpsum[w] = v;
        __syncthreads();
        unsigned int addw = 0;
        for (int j = w + 1; j < 8; j++) addw += warpsum[j];
        unsigned int hs_t = v + addw;
        unsigned int above = hs_t - hv;
        if (hs_t >= (unsigned int)need && above < (unsigned int)need) {
            sb = (unsigned int)t; sabove = above;
        }
        __syncthreads();
        prefix |= sb << shift;
        pmask  |= 0xFFu << shift;
        need   -= (int)sabove;
        __syncthreads();
    }

    if (t == 0) { selCnt = 0; candCnt = 0; needSh = need; }
    __syncthreads();
#pragma unroll
    for (int r = 0; r < 8; r++) {
        int gi = 8 * t + r;
        unsigned int masked = u[r] & pmask;
        if (masked > prefix) {
            int pos = atomicAdd(&selCnt, 1);
            g_idx[row * KNB + pos] = gi;
        } else if (masked == prefix) {
            int pos = atomicAdd(&candCnt, 1);
            cand[pos] = ((unsigned long long)u[r] << 32) | (unsigned int)(2047 - gi);
        }
    }
    __syncthreads();

    if (w == 0) {
        int m = candCnt;
        int base = selCnt;
        int nd = needSh;
        for (int p2 = 0; p2 < nd; p2++) {
            unsigned long long best = 0ull;
            for (int j = lane; j < m; j += 32)
                best = (cand[j] > best) ? cand[j] : best;
#pragma unroll
            for (int s = 16; s; s >>= 1) {
                unsigned long long o = __shfl_xor_sync(0xffffffffu, best, s);
                best = (o > best) ? o : best;
            }
            if (lane == 0)
                g_idx[row * KNB + base + p2] = 2047 - (int)(best & 0xFFFFFFFFull);
            for (int j = lane; j < m; j += 32)
                if (cand[j] == best) cand[j] = 0ull;
        }
    }
}

// ---------------- 5. attention per point: smem K/V staging; K/V centering folded out ----------------
// softmax(q·(k-kc)) == softmax(q·k)  (per-head constant shift)
// sum_k a_k (v_k - vc) == (sum_k a_k v_k) - vc  (since sum a = 1)
__global__ void attn_kernel(const float* __restrict__ x) {
    int row = blockIdx.x;
    int b = row >> 11, n = row & (Nn - 1);
    int t = threadIdx.x;                       // 256 = 8 warps (1 head per warp)
    __shared__ float qv[64];
    __shared__ int   sid[32];
    __shared__ float Ks[32][68];
    __shared__ float Vs[32][68];
    if (t < 32)                   sid[t]     = g_idx[row * KNB + t];
    else if (t >= 64 && t < 128)  qv[t - 64] = g_Qt[(size_t)row * 64 + (t - 64)];
    __syncthreads();

#pragma unroll
    for (int it = 0; it < 2; it++) {
        int idx = t + it * 256;                // 0..511
        int r = idx >> 4, ch = (idx & 15) * 4;
        size_t base = ((size_t)(b * Nn + sid[r])) * 64 + ch;
        *(float4*)&Ks[r][ch] = *(const float4*)&g_Kt[base];
        *(float4*)&Vs[r][ch] = *(const float4*)&g_Vt[base];
    }
    __syncthreads();

    int h = t >> 5, kk = t & 31;
    int h8 = h * 8;
    float4 k0 = *(const float4*)&Ks[kk][h8];
    float4 k1 = *(const float4*)&Ks[kk][h8 + 4];
    float e = 0.f;
    e = fmaf(qv[h8 + 0], k0.x, e);
    e = fmaf(qv[h8 + 1], k0.y, e);
    e = fmaf(qv[h8 + 2], k0.z, e);
    e = fmaf(qv[h8 + 3], k0.w, e);
    e = fmaf(qv[h8 + 4], k1.x, e);
    e = fmaf(qv[h8 + 5], k1.y, e);
    e = fmaf(qv[h8 + 6], k1.z, e);
    e = fmaf(qv[h8 + 7], k1.w, e);
    e *= 0.3535533905932738f;                 // 1/sqrt(8)

    float m = e;
#pragma unroll
    for (int s = 16; s; s >>= 1) m = fmaxf(m, __shfl_xor_sync(0xffffffffu, m, s));
    float ex = __expf(e - m);
    float ssum = ex;
#pragma unroll
    for (int s = 16; s; s >>= 1) ssum += __shfl_xor_sync(0xffffffffu, ssum, s);
    float a = ex / ssum;

    float4 v0 = *(const float4*)&Vs[kk][h8];
    float4 v1 = *(const float4*)&Vs[kk][h8 + 4];
    unsigned long long r0 = pack2(a * v0.x, a * v0.y);
    unsigned long long r1 = pack2(a * v0.z, a * v0.w);
    unsigned long long r2 = pack2(a * v1.x, a * v1.y);
    unsigned long long r3 = pack2(a * v1.z, a * v1.w);
#pragma unroll
    for (int s = 16; s; s >>= 1) {
        r0 = addf2(r0, __shfl_xor_sync(0xffffffffu, r0, s));
        r1 = addf2(r1, __shfl_xor_sync(0xffffffffu, r1, s));
        r2 = addf2(r2, __shfl_xor_sync(0xffffffffu, r2, s));
        r3 = addf2(r3, __shfl_xor_sync(0xffffffffu, r3, s));
    }
    if (kk < 8) {
        unsigned long long sel = (kk < 2) ? r0 : (kk < 4) ? r1 : (kk < 6) ? r2 : r3;
        float lo, hi; unpack2(sel, lo, hi);
        float outv = (kk & 1) ? hi : lo;
        int c = h8 + kk;
        outv -= g_Vt[(size_t)row * 64 + c];    // center-V correction (32B/warp)
        size_t gi = (size_t)b * Cc * Nn + (size_t)c * Nn + n;
        g_y[gi] = x[gi] + outv;
    }
}

// ---------------- 6/8. BN stats, single kernel with last-block finalize ----------------
__global__ void statsA_kernel(int which) {
    const float* in = which ? g_y2 : g_y;
    int c = blockIdx.x, b = blockIdx.y, t = threadIdx.x;
    int lane = t & 31, w = t >> 5;
    const float* p = in + (size_t)b * Cc * Nn + (size_t)c * Nn;
    double s = 0.0, s2 = 0.0;
    for (int n = t; n < Nn; n += 256) { float v = p[n]; s += v; s2 += (double)v * v; }
#pragma unroll
    for (int o = 16; o; o >>= 1) {
        s  += __shfl_down_sync(0xffffffffu, s, o);
        s2 += __shfl_down_sync(0xffffffffu, s2, o);
    }
    __shared__ double ws[8], ws2[8];
    __shared__ int isLast;
    if (lane == 0) { ws[w] = s; ws2[w] = s2; }
    __syncthreads();
    if (t == 0) {
        double ts = 0.0, ts2 = 0.0;
        for (int j = 0; j < 8; j++) { ts += ws[j]; ts2 += ws2[j]; }
        g_ps[which][c][b] = ts;
        g_ps2[which][c][b] = ts2;
        __threadfence();
        int v = atomicAdd(&g_cnt[which], 1);
        isLast = (v == Cc * Bb - 1);
    }
    __syncthreads();
    if (isLast) {
        if (t < Cc) {
            double ts = 0.0, ts2 = 0.0;
            for (int j = 0; j < Bb; j++) { ts += g_ps[which][t][j]; ts2 += g_ps2[which][t][j]; }
            double m = ts / (Bb * Nn);
            double var = ts2 / (Bb * Nn) - m * m;
            (which ? g_mu2 : g_mu1)[t] = (float)m;
            (which ? g_rs2 : g_rs1)[t] = (float)(1.0 / sqrt(var + (double)EPSBN));
        }
        __syncthreads();
        if (t == 0) g_cnt[which] = 0;           // self-reset for next graph replay
    }
}

// ---------------- 7. BN1 apply + FFN + residual ----------------
__global__ void ffn_kernel(const float* __restrict__ W1, const float* __restrict__ W2,
                           const float* __restrict__ g1, const float* __restrict__ b1) {
    int blk = blockIdx.x;
    int b = blk / (Nn / 16);
    int n0 = (blk % (Nn / 16)) * 16;
    __shared__ float Wbuf[128 * 64];
    __shared__ float x1s[64][17];
    __shared__ float hs[128][17];
    int t = threadIdx.x;

    for (int idx = t; idx < 64 * 16; idx += 256) {
        int c = idx >> 4, p = idx & 15;
        float v = g_y[(size_t)b * Cc * Nn + (size_t)c * Nn + n0 + p];
        x1s[c][p] = (v - g_mu1[c]) * g_rs1[c] * g1[c] + b1[c];
    }
    for (int idx = t; idx < 128 * 64; idx += 256) Wbuf[idx] = W1[idx];
    __syncthreads();

    int p = t & 15, obase = t >> 4;
    float hreg[8];
#pragma unroll
    for (int i = 0; i < 8; i++) {
        int o = obase + 16 * i;
        float s = 0.f;
#pragma unroll
        for (int c = 0; c < 64; c++) s = fmaf(Wbuf[o * 64 + c], x1s[c][p], s);
        hreg[i] = (s >= 0.f) ? s : NSLOPE * s;
    }
#pragma unroll
    for (int i = 0; i < 8; i++) hs[obase + 16 * i][p] = hreg[i];
    __syncthreads();
    for (int idx = t; idx < 64 * 128; idx += 256) Wbuf[idx] = W2[idx];
    __syncthreads();

#pragma unroll
    for (int i = 0; i < 4; i++) {
        int c = obase + 16 * i;
        float s = 0.f;
#pragma unroll
        for (int o = 0; o < 128; o++) s = fmaf(Wbuf[c * 128 + o], hs[o][p], s);
        g_y2[(size_t)b * Cc * Nn + (size_t)c * Nn + n0 + p] = x1s[c][p] + s;
    }
}

// ---------------- 9. final BN apply (float4) ----------------
__global__ void apply_kernel(const float* __restrict__ g2, const float* __restrict__ b2,
                             float* __restrict__ out) {
    int i4 = blockIdx.x * blockDim.x + threadIdx.x;      // float4 index
    if (i4 < (Bb * Cc * Nn) / 4) {
        int c = ((i4 * 4) / Nn) & (Cc - 1);
        float4 v = *(const float4*)&g_y2[(size_t)i4 * 4];
        float sc = g_rs2[c] * g2[c], mu = g_mu2[c], bb = b2[c];
        float4 o = make_float4((v.x - mu) * sc + bb, (v.y - mu) * sc + bb,
                               (v.z - mu) * sc + bb, (v.w - mu) * sc + bb);
        *(float4*)&out[(size_t)i4 * 4] = o;
    }
}

// ---------------- launch ----------------
extern "C" void kernel_launch(void* const* d_in, const int* in_sizes, int n_in,
                              void* d_out, int out_size) {
    const float* x  = (const float*)d_in[0];
    const float* Wq = (const float*)d_in[1];
    const float* Wk = (const float*)d_in[2];
    const float* Wv = (const float*)d_in[3];
    const float* W1 = (const float*)d_in[4];
    const float* W2 = (const float*)d_in[5];
    const float* g1 = (const float*)d_in[6];
    const float* b1 = (const float*)d_in[7];
    const float* g2 = (const float*)d_in[8];
    const float* b2 = (const float*)d_in[9];
    float* out = (float*)d_out;

    const int qkv_smem = (64 * 68 + 3 * 64 * 68) * 4;    // 69632 B
    cudaFuncSetAttribute(qkv_kernel, cudaFuncAttributeMaxDynamicSharedMemorySize, qkv_smem);

    qkv_kernel<<<dim3(Nn / 64, Bb), 256, qkv_smem>>>(x, Wq, Wk, Wv);
    dist_kernel<<<dim3(136, 1, Bb), 256>>>(x);
    topk_kernel<<<Bb * Nn, 256>>>();
    attn_kernel<<<Bb * Nn, 256>>>(x);
    statsA_kernel<<<dim3(Cc, Bb), 256>>>(0);
    ffn_kernel<<<Bb * Nn / 16, 256>>>(W1, W2, g1, b1);
    statsA_kernel<<<dim3(Cc, Bb), 256>>>(1);
    apply_kernel<<<(Bb * Cc * Nn / 4 + 255) / 256, 256>>>(g2, b2, out);
}

// round 17
// speedup vs baseline: 1.4639x; 1.0101x over previous
#include <cuda_runtime.h>
#include <math.h>

#define Bb   8
#define Cc   64
#define Nn   2048
#define KNB  32
#define NHEADS 8
#define EPSBN 1e-5f
#define NSLOPE 0.2f

// ---------------- scratch (device globals; no runtime allocation) ----------------
__device__ float g_D[(size_t)Bb * Nn * Nn];             // 128 MB distance matrix
__device__ int   g_idx[Bb * Nn * KNB];
__device__ float g_Qt[(size_t)Bb * Nn * Cc];            // (B,N,64) point-major
__device__ float g_Kt[(size_t)Bb * Nn * Cc];
__device__ float g_Vt[(size_t)Bb * Nn * Cc];
__device__ float g_y [(size_t)Bb * Cc * Nn];
__device__ float g_y2[(size_t)Bb * Cc * Nn];
__device__ float g_mu1[Cc], g_rs1[Cc], g_mu2[Cc], g_rs2[Cc];
__device__ double g_ps [2][Cc][Bb];
__device__ double g_ps2[2][Cc][Bb];
__device__ int    g_cnt[2];                              // zero-init; self-resetting
__device__ int    g_done;                                // rendezvous flag (self-resetting)
__device__ int    g_cnt2;                                // exit counter  (self-resetting)

// ---------------- packed f32x2 helpers (sm_103a FFMA2/FADD2 path) ----------------
__device__ __forceinline__ unsigned long long pack2(float x, float y) {
    unsigned long long r;
    asm("mov.b64 %0, {%1, %2};" : "=l"(r) : "f"(x), "f"(y));
    return r;
}
__device__ __forceinline__ unsigned long long ffma2(unsigned long long a,
                                                    unsigned long long b,
                                                    unsigned long long c) {
    unsigned long long d;
    asm("fma.rn.f32x2 %0, %1, %2, %3;" : "=l"(d) : "l"(a), "l"(b), "l"(c));
    return d;
}
__device__ __forceinline__ unsigned long long addf2(unsigned long long a,
                                                    unsigned long long b) {
    unsigned long long d;
    asm("add.rn.f32x2 %0, %1, %2;" : "=l"(d) : "l"(a), "l"(b));
    return d;
}
__device__ __forceinline__ void unpack2(unsigned long long v, float& lo, float& hi) {
    asm("mov.b64 {%0, %1}, %2;" : "=f"(lo), "=f"(hi) : "l"(v));
}

// ---------------- 1. FUSED: dist blocks (0..1087) + qkv blocks (1088..1343) ----------------
// dist computes its own row/col norms from the staged tiles (same fmaf order as the
// old xx_kernel -> bitwise identical), removing the qkv->dist dependency entirely.
extern __shared__ float dsm[];
__global__ void __launch_bounds__(256, 2) fused_qkv_dist(const float* __restrict__ x,
                                                         const float* __restrict__ Wq,
                                                         const float* __restrict__ Wk,
                                                         const float* __restrict__ Wv) {
    int bid = blockIdx.x;
    int t = threadIdx.x;

    if (bid < 1088) {
        // ================= dist =================
        float (*As)[132] = (float(*)[132])dsm;
        float (*Bs)[132] = (float(*)[132])(dsm + 32 * 132);
        float* xiS = dsm + 2 * 32 * 132;
        float* xjS = xiS + 128;

        int b = bid / 136;
        int p = bid % 136, bi = 0;
        while (p >= 16 - bi) { p -= 16 - bi; bi++; }
        int bj = bi + p;
        int i0 = bi * 128, j0 = bj * 128;

        int tx = t & 15, ty = t >> 4;
        const float* xb = x + (size_t)b * Cc * Nn;

        unsigned long long acc2[4][8];
#pragma unroll
        for (int ip = 0; ip < 4; ip++)
#pragma unroll
            for (int j = 0; j < 8; j++) acc2[ip][j] = 0ull;

        float nrm = 0.f;
        for (int kc = 0; kc < Cc; kc += 32) {
            __syncthreads();
            for (int idx = t; idx < 32 * 128; idx += 256) {
                int c = idx >> 7, q = idx & 127;
                As[c][q] = xb[(kc + c) * Nn + i0 + q];
                Bs[c][q] = xb[(kc + c) * Nn + j0 + q];
            }
            __syncthreads();
            // accumulate squared norms (c ascending: matches old xx_kernel bitwise)
            if (t < 128) {
#pragma unroll
                for (int c = 0; c < 32; c++) { float v = As[c][t]; nrm = fmaf(v, v, nrm); }
            } else {
                int q = t - 128;
#pragma unroll
                for (int c = 0; c < 32; c++) { float v = Bs[c][q]; nrm = fmaf(v, v, nrm); }
            }
#pragma unroll
            for (int c = 0; c < 32; c++) {
                ulonglong2 ap0 = *(const ulonglong2*)&As[c][ty * 8];
                ulonglong2 ap1 = *(const ulonglong2*)&As[c][ty * 8 + 4];
                unsigned long long ap[4] = {ap0.x, ap0.y, ap1.x, ap1.y};
                float4 b0 = *(const float4*)&Bs[c][tx * 8];
                float4 b1 = *(const float4*)&Bs[c][tx * 8 + 4];
                float bv[8] = {b0.x, b0.y, b0.z, b0.w, b1.x, b1.y, b1.z, b1.w};
                unsigned long long bc[8];
#pragma unroll
                for (int j = 0; j < 8; j++) bc[j] = pack2(bv[j], bv[j]);
#pragma unroll
                for (int ip = 0; ip < 4; ip++)
#pragma unroll
                    for (int j = 0; j < 8; j++)
                        acc2[ip][j] = ffma2(ap[ip], bc[j], acc2[ip][j]);
            }
        }
        if (t < 128) xiS[t] = nrm; else xjS[t - 128] = nrm;
        __syncthreads();

        float acc[8][8];
#pragma unroll
        for (int ip = 0; ip < 4; ip++)
#pragma unroll
            for (int j = 0; j < 8; j++)
                unpack2(acc2[ip][j], acc[2 * ip][j], acc[2 * ip + 1][j]);

        float xi[8], xj[8];
#pragma unroll
        for (int ii = 0; ii < 8; ii++) xi[ii] = xiS[ty * 8 + ii];
#pragma unroll
        for (int jj = 0; jj < 8; jj++) xj[jj] = xjS[tx * 8 + jj];

        float v[8][8];
#pragma unroll
        for (int ii = 0; ii < 8; ii++)
#pragma unroll
            for (int jj = 0; jj < 8; jj++)
                v[ii][jj] = 2.f * acc[ii][jj] - xi[ii] - xj[jj];

#pragma unroll
        for (int ii = 0; ii < 8; ii++) {
            size_t base = ((size_t)b * Nn + i0 + ty * 8 + ii) * Nn + j0 + tx * 8;
            *(float4*)&g_D[base]     = make_float4(v[ii][0], v[ii][1], v[ii][2], v[ii][3]);
            *(float4*)&g_D[base + 4] = make_float4(v[ii][4], v[ii][5], v[ii][6], v[ii][7]);
        }
        if (bi != bj) {
#pragma unroll
            for (int jj = 0; jj < 8; jj++) {
                size_t base = ((size_t)b * Nn + j0 + tx * 8 + jj) * Nn + i0 + ty * 8;
                *(float4*)&g_D[base]     = make_float4(v[0][jj], v[1][jj], v[2][jj], v[3][jj]);
                *(float4*)&g_D[base + 4] = make_float4(v[4][jj], v[5][jj], v[6][jj], v[7][jj]);
            }
        }
    } else {
        // ================= qkv =================
        float (*xs)[68] = (float(*)[68])dsm;
        float (*Wt)[68] = (float(*)[68])(dsm + 64 * 68);
        int r = bid - 1088;
        int b = r >> 5, n0 = (r & 31) * 64;
        const float* xb = x + (size_t)b * Cc * Nn;
        for (int idx = t; idx < 4096; idx += 256) {
            int c = idx >> 6, p = idx & 63;
            xs[c][p] = xb[c * Nn + n0 + p];
        }
        const float* Ws[3] = {Wq, Wk, Wv};
#pragma unroll
        for (int m = 0; m < 3; m++)
            for (int idx = t; idx < 4096; idx += 256) {
                int o = idx >> 6, c = idx & 63;
                Wt[m * 64 + c][o] = Ws[m][idx];
            }
        __syncthreads();

        int tx = t & 15, ty = t >> 4;
        float acc[3][4][4] = {};
        for (int c = 0; c < 64; c++) {
            float4 xv4 = *(const float4*)&xs[c][tx * 4];
            float xr[4] = {xv4.x, xv4.y, xv4.z, xv4.w};
#pragma unroll
            for (int m = 0; m < 3; m++) {
                float4 wv4 = *(const float4*)&Wt[m * 64 + c][ty * 4];
                float wr[4] = {wv4.x, wv4.y, wv4.z, wv4.w};
#pragma unroll
                for (int oi = 0; oi < 4; oi++)
#pragma unroll
                    for (int pj = 0; pj < 4; pj++)
                        acc[m][oi][pj] = fmaf(wr[oi], xr[pj], acc[m][oi][pj]);
            }
        }
        float* Olist[3] = {g_Qt, g_Kt, g_Vt};
#pragma unroll
        for (int m = 0; m < 3; m++)
#pragma unroll
            for (int pj = 0; pj < 4; pj++) {
                int p = n0 + tx * 4 + pj;
                float4 val = make_float4(acc[m][0][pj], acc[m][1][pj], acc[m][2][pj], acc[m][3][pj]);
                *(float4*)&Olist[m][((size_t)(b * Nn + p)) * 64 + ty * 4] = val;
            }
    }
}

// ---------------- 3. top-32 per row: 2-level radix + warp micro-select ----------------
__global__ void topk_kernel() {
    int row = blockIdx.x;
    int t = threadIdx.x;                    // 256 threads
    int lane = t & 31, w = t >> 5;
    const float* Drow = g_D + (size_t)row * Nn;

    unsigned int u[8];
    {
        float4 f0 = *(const float4*)(Drow + 8 * t);
        float4 f1 = *(const float4*)(Drow + 8 * t + 4);
        float fv[8] = {f0.x, f0.y, f0.z, f0.w, f1.x, f1.y, f1.z, f1.w};
#pragma unroll
        for (int r = 0; r < 8; r++) {
            unsigned int bits = __float_as_uint(fv[r]);
            u[r] = (bits & 0x80000000u) ? ~bits : (bits | 0x80000000u);
        }
    }

    __shared__ unsigned int hist[256];
    __shared__ unsigned int warpsum[8];
    __shared__ unsigned int sb, sabove;
    __shared__ unsigned long long cand[2048];
    __shared__ int selCnt, candCnt, needSh;

    unsigned int prefix = 0, pmask = 0;
    int need = KNB;

#pragma unroll
    for (int lvl = 0; lvl < 2; lvl++) {
        int shift = 24 - 8 * lvl;
        hist[t] = 0;
        __syncthreads();
#pragma unroll
        for (int r = 0; r < 8; r++)
            if ((u[r] & pmask) == prefix)
                atomicAdd(&hist[(u[r] >> shift) & 255u], 1u);
        __syncthreads();
        unsigned int hv = hist[t];
        unsigned int v = hv;
#pragma unroll
        for (int s = 1; s < 32; s <<= 1) {
            unsigned int o = __shfl_down_sync(0xffffffffu, v, s);
            if (lane + s < 32) v += o;
        }
        if (lane == 0) warpsum[w] = v;
        __syncthreads();
        unsigned int addw = 0;
        for (int j = w + 1; j < 8; j++) addw += warpsum[j];
        unsigned int hs_t = v + addw;
        unsigned int above = hs_t - hv;
        if (hs_t >= (unsigned int)need && above < (unsigned int)need) {
            sb = (unsigned int)t; sabove = above;
        }
        __syncthreads();
        prefix |= sb << shift;
        pmask  |= 0xFFu << shift;
        need   -= (int)sabove;
        __syncthreads();
    }

    if (t == 0) { selCnt = 0; candCnt = 0; needSh = need; }
    __syncthreads();
#pragma unroll
    for (int r = 0; r < 8; r++) {
        int gi = 8 * t + r;
        unsigned int masked = u[r] & pmask;
        if (masked > prefix) {
            int pos = atomicAdd(&selCnt, 1);
            g_idx[row * KNB + pos] = gi;
        } else if (masked == prefix) {
            int pos = atomicAdd(&candCnt, 1);
            cand[pos] = ((unsigned long long)u[r] << 32) | (unsigned int)(2047 - gi);
        }
    }
    __syncthreads();

    if (w == 0) {
        int m = candCnt;
        int base = selCnt;
        int nd = needSh;
        for (int p2 = 0; p2 < nd; p2++) {
            unsigned long long best = 0ull;
            for (int j = lane; j < m; j += 32)
                best = (cand[j] > best) ? cand[j] : best;
#pragma unroll
            for (int s = 16; s; s >>= 1) {
                unsigned long long o = __shfl_xor_sync(0xffffffffu, best, s);
                best = (o > best) ? o : best;
            }
            if (lane == 0)
                g_idx[row * KNB + base + p2] = 2047 - (int)(best & 0xFFFFFFFFull);
            for (int j = lane; j < m; j += 32)
                if (cand[j] == best) cand[j] = 0ull;
        }
    }
}

// ---------------- 5. attention per point (converged R14/R16 version) ----------------
__global__ void attn_kernel(const float* __restrict__ x) {
    int row = blockIdx.x;
    int b = row >> 11, n = row & (Nn - 1);
    int t = threadIdx.x;                       // 256 = 8 warps (1 head per warp)
    __shared__ float qv[64];
    __shared__ int   sid[32];
    __shared__ float Ks[32][68];
    __shared__ float Vs[32][68];
    if (t < 32)                   sid[t]     = g_idx[row * KNB + t];
    else if (t >= 64 && t < 128)  qv[t - 64] = g_Qt[(size_t)row * 64 + (t - 64)];
    __syncthreads();

#pragma unroll
    for (int it = 0; it < 2; it++) {
        int idx = t + it * 256;                // 0..511
        int r = idx >> 4, ch = (idx & 15) * 4;
        size_t base = ((size_t)(b * Nn + sid[r])) * 64 + ch;
        *(float4*)&Ks[r][ch] = *(const float4*)&g_Kt[base];
        *(float4*)&Vs[r][ch] = *(const float4*)&g_Vt[base];
    }
    __syncthreads();

    int h = t >> 5, kk = t & 31;
    int h8 = h * 8;
    float4 k0 = *(const float4*)&Ks[kk][h8];
    float4 k1 = *(const float4*)&Ks[kk][h8 + 4];
    float e = 0.f;
    e = fmaf(qv[h8 + 0], k0.x, e);
    e = fmaf(qv[h8 + 1], k0.y, e);
    e = fmaf(qv[h8 + 2], k0.z, e);
    e = fmaf(qv[h8 + 3], k0.w, e);
    e = fmaf(qv[h8 + 4], k1.x, e);
    e = fmaf(qv[h8 + 5], k1.y, e);
    e = fmaf(qv[h8 + 6], k1.z, e);
    e = fmaf(qv[h8 + 7], k1.w, e);
    e *= 0.3535533905932738f;                 // 1/sqrt(8)

    float m = e;
#pragma unroll
    for (int s = 16; s; s >>= 1) m = fmaxf(m, __shfl_xor_sync(0xffffffffu, m, s));
    float ex = __expf(e - m);
    float ssum = ex;
#pragma unroll
    for (int s = 16; s; s >>= 1) ssum += __shfl_xor_sync(0xffffffffu, ssum, s);
    float a = ex / ssum;

    float4 v0 = *(const float4*)&Vs[kk][h8];
    float4 v1 = *(const float4*)&Vs[kk][h8 + 4];
    unsigned long long r0 = pack2(a * v0.x, a * v0.y);
    unsigned long long r1 = pack2(a * v0.z, a * v0.w);
    unsigned long long r2 = pack2(a * v1.x, a * v1.y);
    unsigned long long r3 = pack2(a * v1.z, a * v1.w);
#pragma unroll
    for (int s = 16; s; s >>= 1) {
        r0 = addf2(r0, __shfl_xor_sync(0xffffffffu, r0, s));
        r1 = addf2(r1, __shfl_xor_sync(0xffffffffu, r1, s));
        r2 = addf2(r2, __shfl_xor_sync(0xffffffffu, r2, s));
        r3 = addf2(r3, __shfl_xor_sync(0xffffffffu, r3, s));
    }
    if (kk < 8) {
        unsigned long long sel = (kk < 2) ? r0 : (kk < 4) ? r1 : (kk < 6) ? r2 : r3;
        float lo, hi; unpack2(sel, lo, hi);
        float outv = (kk & 1) ? hi : lo;
        int c = h8 + kk;
        outv -= g_Vt[(size_t)row * 64 + c];    // center-V correction (32B/warp)
        size_t gi = (size_t)b * Cc * Nn + (size_t)c * Nn + n;
        g_y[gi] = x[gi] + outv;
    }
}

// ---------------- 6/8. BN stats; which==1 also applies BN2 in-kernel after a
// device-wide rendezvous (all 512 blocks provably co-resident: 8/SM x 148 >= 512) ----------------
__global__ void statsA_kernel(int which, int doApply,
                              const float* __restrict__ g2, const float* __restrict__ b2,
                              float* __restrict__ out) {
    const float* in = which ? g_y2 : g_y;
    int c = blockIdx.x, b = blockIdx.y, t = threadIdx.x;
    int lane = t & 31, w = t >> 5;
    const float* p = in + (size_t)b * Cc * Nn + (size_t)c * Nn;
    double s = 0.0, s2 = 0.0;
#pragma unroll
    for (int i = 0; i < 2; i++) {
        float4 v4 = *(const float4*)&p[t * 8 + i * 4];
        s += (double)v4.x + (double)v4.y + (double)v4.z + (double)v4.w;
        s2 += (double)v4.x * v4.x + (double)v4.y * v4.y
            + (double)v4.z * v4.z + (double)v4.w * v4.w;
    }
#pragma unroll
    for (int o = 16; o; o >>= 1) {
        s  += __shfl_down_sync(0xffffffffu, s, o);
        s2 += __shfl_down_sync(0xffffffffu, s2, o);
    }
    __shared__ double ws[8], ws2[8];
    __shared__ int isLast;
    if (lane == 0) { ws[w] = s; ws2[w] = s2; }
    __syncthreads();
    if (t == 0) {
        double ts = 0.0, ts2 = 0.0;
        for (int j = 0; j < 8; j++) { ts += ws[j]; ts2 += ws2[j]; }
        g_ps[which][c][b] = ts;
        g_ps2[which][c][b] = ts2;
        __threadfence();
        int v = atomicAdd(&g_cnt[which], 1);
        isLast = (v == Cc * Bb - 1);
    }
    __syncthreads();
    if (isLast) {
        if (t < Cc) {
            double ts = 0.0, ts2 = 0.0;
            for (int j = 0; j < Bb; j++) { ts += g_ps[which][t][j]; ts2 += g_ps2[which][t][j]; }
            double m = ts / (Bb * Nn);
            double var = ts2 / (Bb * Nn) - m * m;
            (which ? g_mu2 : g_mu1)[t] = (float)m;
            (which ? g_rs2 : g_rs1)[t] = (float)(1.0 / sqrt(var + (double)EPSBN));
        }
        __syncthreads();
        if (t == 0) {
            g_cnt[which] = 0;                   // self-reset for next graph replay
            __threadfence();
            if (doApply) atomicExch(&g_done, 1);
        }
    }
    if (!doApply) return;

    // rendezvous: wait for mu2/rs2 publication
    if (t == 0) { while (atomicAdd(&g_done, 0) == 0) __nanosleep(100); }
    __syncthreads();
    __threadfence();

    // apply BN2 to this block's (c,b) stripe (fully coalesced)
    {
        float mu = g_mu2[c], sc = g_rs2[c] * g2[c], bb = b2[c];
        const float* src = g_y2 + (size_t)b * Cc * Nn + (size_t)c * Nn;
        float*       dst = out  + (size_t)b * Cc * Nn + (size_t)c * Nn;
#pragma unroll
        for (int i = 0; i < 2; i++) {
            float4 v4 = *(const float4*)&src[t * 8 + i * 4];
            float4 o4 = make_float4((v4.x - mu) * sc + bb, (v4.y - mu) * sc + bb,
                                    (v4.z - mu) * sc + bb, (v4.w - mu) * sc + bb);
            *(float4*)&dst[t * 8 + i * 4] = o4;
        }
    }
    __syncthreads();
    if (t == 0) {                               // last block out resets the flag
        int v2 = atomicAdd(&g_cnt2, 1);
        if (v2 == Cc * Bb - 1) { g_done = 0; g_cnt2 = 0; }
    }
}

// ---------------- 7. BN1 apply + FFN + residual ----------------
__global__ void ffn_kernel(const float* __restrict__ W1, const float* __restrict__ W2,
                           const float* __restrict__ g1, const float* __restrict__ b1) {
    int blk = blockIdx.x;
    int b = blk / (Nn / 16);
    int n0 = (blk % (Nn / 16)) * 16;
    __shared__ float Wbuf[128 * 64];
    __shared__ float x1s[64][17];
    __shared__ float hs[128][17];
    int t = threadIdx.x;

    for (int idx = t; idx < 64 * 16; idx += 256) {
        int c = idx >> 4, p = idx & 15;
        float v = g_y[(size_t)b * Cc * Nn + (size_t)c * Nn + n0 + p];
        x1s[c][p] = (v - g_mu1[c]) * g_rs1[c] * g1[c] + b1[c];
    }
    for (int idx = t; idx < 128 * 64; idx += 256) Wbuf[idx] = W1[idx];
    __syncthreads();

    int p = t & 15, obase = t >> 4;
    float hreg[8];
#pragma unroll
    for (int i = 0; i < 8; i++) {
        int o = obase + 16 * i;
        float s = 0.f;
#pragma unroll
        for (int c = 0; c < 64; c++) s = fmaf(Wbuf[o * 64 + c], x1s[c][p], s);
        hreg[i] = (s >= 0.f) ? s : NSLOPE * s;
    }
#pragma unroll
    for (int i = 0; i < 8; i++) hs[obase + 16 * i][p] = hreg[i];
    __syncthreads();
    for (int idx = t; idx < 64 * 128; idx += 256) Wbuf[idx] = W2[idx];
    __syncthreads();

#pragma unroll
    for (int i = 0; i < 4; i++) {
        int c = obase + 16 * i;
        float s = 0.f;
#pragma unroll
        for (int o = 0; o < 128; o++) s = fmaf(Wbuf[c * 128 + o], hs[o][p], s);
        g_y2[(size_t)b * Cc * Nn + (size_t)c * Nn + n0 + p] = x1s[c][p] + s;
    }
}

// ---------------- launch ----------------
extern "C" void kernel_launch(void* const* d_in, const int* in_sizes, int n_in,
                              void* d_out, int out_size) {
    const float* x  = (const float*)d_in[0];
    const float* Wq = (const float*)d_in[1];
    const float* Wk = (const float*)d_in[2];
    const float* Wv = (const float*)d_in[3];
    const float* W1 = (const float*)d_in[4];
    const float* W2 = (const float*)d_in[5];
    const float* g1 = (const float*)d_in[6];
    const float* b1 = (const float*)d_in[7];
    const float* g2 = (const float*)d_in[8];
    const float* b2 = (const float*)d_in[9];
    float* out = (float*)d_out;

    const int fused_smem = (64 * 68 + 3 * 64 * 68) * 4;   // 69632 B (covers both branches)
    cudaFuncSetAttribute(fused_qkv_dist, cudaFuncAttributeMaxDynamicSharedMemorySize, fused_smem);

    fused_qkv_dist<<<1088 + 256, 256, fused_smem>>>(x, Wq, Wk, Wv);
    topk_kernel<<<Bb * Nn, 256>>>();
    attn_kernel<<<Bb * Nn, 256>>>(x);
    statsA_kernel<<<dim3(Cc, Bb), 256>>>(0, 0, nullptr, nullptr, nullptr);
    ffn_kernel<<<Bb * Nn / 16, 256>>>(W1, W2, g1, b1);
    statsA_kernel<<<dim3(Cc, Bb), 256>>>(1, 1, g2, b2, out);
}